// round 16
// baseline (speedup 1.0000x reference)
#include <cuda_runtime.h>
#include <math_constants.h>

// Problem constants
#define BB 128
#define CC 3
#define HH 256
#define WW 256
#define NSTEPS 64
#define NT 256                   // 8 warps: 4 row-strips x 2 half-rows
#define RB_PER_IMG 2             // row-blocks per image (128 rows: 4 strips of 32)
#define ROWS_PER_STRIP 32
#define NIMG (BB*CC)             // 384
#define NCTA (NIMG*RB_PER_IMG)   // 768
#define NBINS 65                 // 64 real + 1 trash
#define CSTRIDE 258              // shorts; 129 words, odd -> near-conflict-free banks

// Deterministic per-CTA partial histograms (every slot written every launch).
__device__ int g_part[NCTA * NSTEPS];

// Single-instruction 0/-1 masks (FSET), avoiding FSETP+SEL pairs.
__device__ __forceinline__ int mask_le(float a, float b) {   // -(a <= b)
    int m;
    asm("set.le.s32.f32 %0, %1, %2;" : "=r"(m) : "f"(a), "f"(b));
    return m;
}
__device__ __forceinline__ int mask_lt(float a, float b) {   // -(a < b)
    int m;
    asm("set.lt.s32.f32 %0, %1, %2;" : "=r"(m) : "f"(a), "f"(b));
    return m;
}

// bin = clip(ceil((f - 0.02)/RES), 0, 63); f > 0.98 (incl. INF sentinel) -> 64 (trash).
__device__ __forceinline__ int bin_of(float f) {
    constexpr double RES_D = (0.98 - 0.02) / 63.0;
    constexpr float RINV = (float)(1.0 / RES_D);
    constexpr float C    = (float)(-0.02 / RES_D);
    unsigned b = __float2uint_ru(fmaf(f, RINV, C));   // negatives saturate to 0
    return (int)min(b, (unsigned)(NBINS - 1));
}

struct Raw { float4 v; float b; };        // b: lane0 = left boundary, lane31 = right
struct R4  { float l; float4 v; float r; };

// Prefetch stage: vector load + one predicated boundary scalar (lanes 0/31 only).
__device__ __forceinline__ Raw load_raw(const float* p, int lane,
                                        bool leftEdge, bool rightEdge) {
    Raw r;
    r.v = __ldg((const float4*)p);
    r.b = CUDART_INF_F;
    if (lane == 0)  { if (!leftEdge)  r.b = __ldg(p - 1); }
    else if (lane == 31) { if (!rightEdge) r.b = __ldg(p + 4); }
    return r;
}

__device__ __forceinline__ Raw inf_raw() {
    Raw r; r.b = CUDART_INF_F;
    r.v = make_float4(CUDART_INF_F, CUDART_INF_F, CUDART_INF_F, CUDART_INF_F);
    return r;
}

// Resolve stage (one iteration after the load -> SHFL never waits on LDG).
__device__ __forceinline__ R4 resolve(const Raw& w, int lane) {
    R4 r; r.v = w.v;
    float lv = __shfl_up_sync(0xFFFFFFFFu, w.v.w, 1);
    float rv = __shfl_down_sync(0xFFFFFFFFu, w.v.x, 1);
    if (lane == 0)  lv = w.b;
    if (lane == 31) rv = w.b;
    r.l = lv; r.r = rv;
    return r;
}

// All-ones dominance masks. Position tiebreak: earlier neighbors (L,U,UL,UR)
// use <=, later (R,D,DL,DR) use <. INF sentinels never dominated.
__device__ __forceinline__ void pix(short* __restrict__ c, float v,
                                    int mL, int mR,
                                    float u, float ul, float ur,
                                    float d, float dl, float dr) {
    int mU  = mask_le(u,  v);
    int mUL = mask_le(ul, v);
    int mUR = mask_le(ur, v);
    int mD  = mask_lt(d,  v);
    int mDL = mask_lt(dl, v);
    int mDR = mask_lt(dr, v);
    int w = 1 + mL + mR + mU + mD
          - (mL & mU & mUL) - (mR & mU & mUR)
          - (mL & mD & mDL) - (mR & mD & mDR);
    c[bin_of(v) * CSTRIDE] += (short)w;
}

__device__ __forceinline__ void proc4(short* __restrict__ c,
                                      const R4& up, const R4& cu, const R4& dn) {
    int h0 = mask_le(cu.l,   cu.v.x);
    int h1 = mask_le(cu.v.x, cu.v.y);
    int h2 = mask_le(cu.v.y, cu.v.z);
    int h3 = mask_le(cu.v.z, cu.v.w);
    int h4 = mask_lt(cu.r,   cu.v.w);    // right-of-pixel3 (later -> <)

    pix(c, cu.v.x, h0, ~h1, up.v.x, up.l,   up.v.y, dn.v.x, dn.l,   dn.v.y);
    pix(c, cu.v.y, h1, ~h2, up.v.y, up.v.x, up.v.z, dn.v.y, dn.v.x, dn.v.z);
    pix(c, cu.v.z, h2, ~h3, up.v.z, up.v.y, up.v.w, dn.v.z, dn.v.y, dn.v.w);
    pix(c, cu.v.w, h3, h4,  up.v.w, up.v.z, up.r,   dn.v.w, dn.v.z, dn.r);
}

__global__ void __launch_bounds__(NT, 5)
ecc_main(const float* __restrict__ x) {
    __shared__ short cnt[NBINS * CSTRIDE];   // 32.7 KB

    const int tid = threadIdx.x;
    { // zero (65*258 shorts = 8385 ints), bounds-checked
        int* ci = (int*)cnt;
        for (int i = tid; i < (NBINS * CSTRIDE) / 2; i += NT) ci[i] = 0;
    }
    __syncthreads();

    const int img   = blockIdx.x >> 1;
    const int rb    = blockIdx.x & 1;
    const int wrp   = tid >> 5;
    const int lane  = tid & 31;
    const int strip = wrp >> 1;              // 0..3
    const int half  = wrp & 1;               // 0: cols 0-127, 1: cols 128-255
    const int g0    = rb * 128 + strip * ROWS_PER_STRIP;
    const int col   = half * 128 + lane * 4;
    const bool leftEdge  = (half == 0);
    const bool rightEdge = (half == 1);
    const float* p  = x + (size_t)img * (HH * WW) + g0 * WW + col;

    short* c = cnt + tid;

    Raw r_up = (g0 > 0) ? load_raw(p - WW, lane, leftEdge, rightEdge) : inf_raw();
    Raw r_cu = load_raw(p, lane, leftEdge, rightEdge);
    Raw r_dn = load_raw(p + WW, lane, leftEdge, rightEdge);   // row g0+1 (< HH always)

    R4 up = resolve(r_up, lane);
    R4 cu = resolve(r_cu, lane);

    // Prefetch at iteration i targets row g0+i+2; valid iff i <= HH-g0-3.
    const int limit = HH - g0 - 3;

#pragma unroll 2
    for (int i = 0; i < ROWS_PER_STRIP; ++i) {
        Raw r_nx = (i <= limit) ? load_raw(p + 2 * WW, lane, leftEdge, rightEdge)
                                : inf_raw();
        R4 dn = resolve(r_dn, lane);         // loaded last iteration: no LDG stall
        proc4(c, up, cu, dn);
        up = cu; cu = dn; r_dn = r_nx; p += WW;
    }

    __syncthreads();

    // CTA reduction: warp w handles bins [w*8, w*8+8); trash bin 64 dropped.
    int* outp = g_part + blockIdx.x * NSTEPS;
#pragma unroll
    for (int k = 0; k < 8; ++k) {
        const int bnum = wrp * 8 + k;
        int s = 0;
#pragma unroll
        for (int j = 0; j < NT / 32; ++j)
            s += (int)cnt[bnum * CSTRIDE + j * 32 + lane];
#pragma unroll
        for (int off = 16; off; off >>= 1)
            s += __shfl_xor_sync(0xFFFFFFFFu, s, off);
        if (lane == 0) outp[bnum] = s;
    }
}

// One warp per image: sum 2 row-block partials, inclusive-scan 64 bins, emit f32.
__global__ void __launch_bounds__(32)
ecc_final(float* __restrict__ out) {
    const int lane = threadIdx.x;
    const int img  = blockIdx.x;

    const int* p = g_part + (size_t)img * RB_PER_IMG * NSTEPS;
    int s0 = 0, s1 = 0;
#pragma unroll
    for (int rb = 0; rb < RB_PER_IMG; ++rb) {
        s0 += __ldg(p + rb * NSTEPS + lane);
        s1 += __ldg(p + rb * NSTEPS + lane + 32);
    }

    int v0 = s0;
#pragma unroll
    for (int off = 1; off < 32; off <<= 1) {
        int t = __shfl_up_sync(0xFFFFFFFFu, v0, off);
        if (lane >= off) v0 += t;
    }
    int tot = __shfl_sync(0xFFFFFFFFu, v0, 31);
    int v1 = s1;
#pragma unroll
    for (int off = 1; off < 32; off <<= 1) {
        int t = __shfl_up_sync(0xFFFFFFFFu, v1, off);
        if (lane >= off) v1 += t;
    }
    v1 += tot;

    out[(size_t)img * NSTEPS + lane]      = (float)v0;
    out[(size_t)img * NSTEPS + lane + 32] = (float)v1;
}

extern "C" void kernel_launch(void* const* d_in, const int* in_sizes, int n_in,
                              void* d_out, int out_size) {
    (void)in_sizes; (void)n_in; (void)out_size;
    const float* x = (const float*)d_in[0];
    float* out = (float*)d_out;

    ecc_main<<<NCTA, NT>>>(x);
    ecc_final<<<NIMG, 32>>>(out);
}

// round 17
// speedup vs baseline: 1.2251x; 1.2251x over previous
#include <cuda_runtime.h>
#include <math_constants.h>

// Problem constants
#define BB 128
#define CC 3
#define HH 256
#define WW 256
#define NSTEPS 64
#define NT 256                   // 8 warps: 4 row-strips x 2 half-rows
#define RB_PER_IMG 2             // row-blocks per image (128 rows: 4 strips of 32)
#define ROWS_PER_STRIP 32
#define NIMG (BB*CC)             // 384
#define NCTA (NIMG*RB_PER_IMG)   // 768
#define NBINS 65                 // 64 real + 1 trash
#define CSTRIDE 258              // shorts; 129 words, odd -> near-conflict-free banks

// Deterministic per-CTA partial histograms (every slot written every launch).
__device__ int g_part[NCTA * NSTEPS];

// bin = clip(ceil((f - 0.02)/RES), 0, 63); f > 0.98 (incl. INF sentinel) -> 64 (trash).
__device__ __forceinline__ int bin_of(float f) {
    constexpr double RES_D = (0.98 - 0.02) / 63.0;
    constexpr float RINV = (float)(1.0 / RES_D);
    constexpr float C    = (float)(-0.02 / RES_D);
    unsigned b = __float2uint_ru(fmaf(f, RINV, C));   // negatives saturate to 0
    return (int)min(b, (unsigned)(NBINS - 1));
}

struct Raw { float4 v; float b; };        // b: lane0 = left boundary, lane31 = right
struct R4  { float l; float4 v; float r; };

// Prefetch stage: vector load + ONE predicated boundary scalar, branchless.
__device__ __forceinline__ Raw load_raw(const float* p, int lane,
                                        bool leftEdge, bool rightEdge) {
    Raw r;
    r.v = __ldg((const float4*)p);
    const bool isL = (lane == 0), isR = (lane == 31);
    const float* bp = isL ? (p - 1) : (p + 4);
    const bool want = (isL && !leftEdge) || (isR && !rightEdge);
    r.b = want ? __ldg(bp) : CUDART_INF_F;   // predicated LDG, no divergent branch
    return r;
}

__device__ __forceinline__ Raw inf_raw() {
    Raw r; r.b = CUDART_INF_F;
    r.v = make_float4(CUDART_INF_F, CUDART_INF_F, CUDART_INF_F, CUDART_INF_F);
    return r;
}

// Resolve stage (one iteration after the load -> SHFL never waits on LDG).
__device__ __forceinline__ R4 resolve(const Raw& w, int lane) {
    R4 r; r.v = w.v;
    float lv = __shfl_up_sync(0xFFFFFFFFu, w.v.w, 1);
    float rv = __shfl_down_sync(0xFFFFFFFFu, w.v.x, 1);
    if (lane == 0)  lv = w.b;
    if (lane == 31) rv = w.b;
    r.l = lv; r.r = rv;
    return r;
}

// All-ones dominance masks. Position tiebreak: earlier neighbors (L,U,UL,UR)
// use <=, later (R,D,DL,DR) use <. INF sentinels never dominated.
__device__ __forceinline__ void pix(short* __restrict__ c, float v,
                                    int mL, int mR,
                                    float u, float ul, float ur,
                                    float d, float dl, float dr) {
    int mU  = -(int)(u  <= v);
    int mUL = -(int)(ul <= v);
    int mUR = -(int)(ur <= v);
    int mD  = -(int)(d  <  v);
    int mDL = -(int)(dl <  v);
    int mDR = -(int)(dr <  v);
    int w = 1 + mL + mR + mU + mD
          - (mL & mU & mUL) - (mR & mU & mUR)
          - (mL & mD & mDL) - (mR & mD & mDR);
    c[bin_of(v) * CSTRIDE] += (short)w;
}

__device__ __forceinline__ void proc4(short* __restrict__ c,
                                      const R4& up, const R4& cu, const R4& dn) {
    int h0 = -(int)(cu.l   <= cu.v.x);
    int h1 = -(int)(cu.v.x <= cu.v.y);
    int h2 = -(int)(cu.v.y <= cu.v.z);
    int h3 = -(int)(cu.v.z <= cu.v.w);
    int h4 = -(int)(cu.r   <  cu.v.w);   // right-of-pixel3 (later -> <)

    pix(c, cu.v.x, h0, ~h1, up.v.x, up.l,   up.v.y, dn.v.x, dn.l,   dn.v.y);
    pix(c, cu.v.y, h1, ~h2, up.v.y, up.v.x, up.v.z, dn.v.y, dn.v.x, dn.v.z);
    pix(c, cu.v.z, h2, ~h3, up.v.z, up.v.y, up.v.w, dn.v.z, dn.v.y, dn.v.w);
    pix(c, cu.v.w, h3, h4,  up.v.w, up.v.z, up.r,   dn.v.w, dn.v.z, dn.r);
}

__global__ void __launch_bounds__(NT, 5)
ecc_main(const float* __restrict__ x) {
    __shared__ short cnt[NBINS * CSTRIDE];   // 32.7 KB

    const int tid = threadIdx.x;
    { // zero (65*258 shorts = 8385 ints), bounds-checked
        int* ci = (int*)cnt;
        for (int i = tid; i < (NBINS * CSTRIDE) / 2; i += NT) ci[i] = 0;
    }
    __syncthreads();

    const int img   = blockIdx.x >> 1;
    const int rb    = blockIdx.x & 1;
    const int wrp   = tid >> 5;
    const int lane  = tid & 31;
    const int strip = wrp >> 1;              // 0..3
    const int half  = wrp & 1;               // 0: cols 0-127, 1: cols 128-255
    const int g0    = rb * 128 + strip * ROWS_PER_STRIP;
    const int col   = half * 128 + lane * 4;
    const bool leftEdge  = (half == 0);
    const bool rightEdge = (half == 1);
    const float* p  = x + (size_t)img * (HH * WW) + g0 * WW + col;

    short* c = cnt + tid;

    Raw r_up = (g0 > 0) ? load_raw(p - WW, lane, leftEdge, rightEdge) : inf_raw();
    Raw r_cu = load_raw(p, lane, leftEdge, rightEdge);
    Raw r_dn = load_raw(p + WW, lane, leftEdge, rightEdge);   // row g0+1 (< HH always)

    R4 up = resolve(r_up, lane);
    R4 cu = resolve(r_cu, lane);

    // Iterations 0..29 prefetch rows g0+2 .. g0+31 — always inside the strip's
    // image rows (g0+31 <= 255 for every strip). No guard needed.
#pragma unroll 2
    for (int i = 0; i < ROWS_PER_STRIP - 2; ++i) {
        Raw r_nx = load_raw(p + 2 * WW, lane, leftEdge, rightEdge);
        R4 dn = resolve(r_dn, lane);         // loaded last iteration: no LDG stall
        proc4(c, up, cu, dn);
        up = cu; cu = dn; r_dn = r_nx; p += WW;
    }
    { // i = 30: prefetch row g0+32 (next strip's first row) unless image edge
        Raw r_nx = (g0 + 32 < HH) ? load_raw(p + 2 * WW, lane, leftEdge, rightEdge)
                                  : inf_raw();
        R4 dn = resolve(r_dn, lane);
        proc4(c, up, cu, dn);
        up = cu; cu = dn; r_dn = r_nx; p += WW;
    }
    { // i = 31: no prefetch (result would be dead)
        R4 dn = resolve(r_dn, lane);
        proc4(c, up, cu, dn);
    }

    __syncthreads();

    // CTA reduction: warp w handles bins [w*8, w*8+8); trash bin 64 dropped.
    int* outp = g_part + blockIdx.x * NSTEPS;
#pragma unroll
    for (int k = 0; k < 8; ++k) {
        const int bnum = wrp * 8 + k;
        int s = 0;
#pragma unroll
        for (int j = 0; j < NT / 32; ++j)
            s += (int)cnt[bnum * CSTRIDE + j * 32 + lane];
#pragma unroll
        for (int off = 16; off; off >>= 1)
            s += __shfl_xor_sync(0xFFFFFFFFu, s, off);
        if (lane == 0) outp[bnum] = s;
    }
}

// One warp per image: sum 2 row-block partials, inclusive-scan 64 bins, emit f32.
__global__ void __launch_bounds__(32)
ecc_final(float* __restrict__ out) {
    const int lane = threadIdx.x;
    const int img  = blockIdx.x;

    const int* p = g_part + (size_t)img * RB_PER_IMG * NSTEPS;
    int s0 = 0, s1 = 0;
#pragma unroll
    for (int rb = 0; rb < RB_PER_IMG; ++rb) {
        s0 += __ldg(p + rb * NSTEPS + lane);
        s1 += __ldg(p + rb * NSTEPS + lane + 32);
    }

    int v0 = s0;
#pragma unroll
    for (int off = 1; off < 32; off <<= 1) {
        int t = __shfl_up_sync(0xFFFFFFFFu, v0, off);
        if (lane >= off) v0 += t;
    }
    int tot = __shfl_sync(0xFFFFFFFFu, v0, 31);
    int v1 = s1;
#pragma unroll
    for (int off = 1; off < 32; off <<= 1) {
        int t = __shfl_up_sync(0xFFFFFFFFu, v1, off);
        if (lane >= off) v1 += t;
    }
    v1 += tot;

    out[(size_t)img * NSTEPS + lane]      = (float)v0;
    out[(size_t)img * NSTEPS + lane + 32] = (float)v1;
}

extern "C" void kernel_launch(void* const* d_in, const int* in_sizes, int n_in,
                              void* d_out, int out_size) {
    (void)in_sizes; (void)n_in; (void)out_size;
    const float* x = (const float*)d_in[0];
    float* out = (float*)d_out;

    ecc_main<<<NCTA, NT>>>(x);
    ecc_final<<<NIMG, 32>>>(out);
}